// round 12
// baseline (speedup 1.0000x reference)
#include <cuda_runtime.h>

// Shapes (fixed by the problem)
#define Bb 256
#define Cc 256
#define CH 128
#define NN 196               // H*W = 14*14
#define N4 49                // float4s per channel row
#define EPS 1e-5f

#define K1_GRID 2048         // block = (batch, 32-channel slice)
#define K2_GRID 2048         // block = (batch, 32-channel slice)

// Scratch (__device__ globals; fully overwritten per launch -> replay-safe)
// g_tmp_part[bid][ch]: partial of tmp[b,ch] = (Wv @ ysum[b])[ch] from slice grp.
__device__ float g_tmp_part[K1_GRID * CH];   // 1 MB

// ---------------------------------------------------------------------------
// Math: softmax over a singleton axis == 1 -> attention collapses to the
// spatial sum (Wq, Wk dead):
//   tmp[b]   = Wv @ (sum_n y[b,:,n])
//   zbn[b,o] = BN( Wz[o,:] . tmp[b] );   out = x + bcast(zbn)
// tmp distributes over 32-channel slices -> no cross-block dependency in K1.
// ---------------------------------------------------------------------------

// K1: block bid covers rows [bid*32, bid*32+32). 8 warps x 4 rows, 8
// front-batched LDG.128 per thread (MLP_p1=8), then the Wv-slice partial.
__global__ void __launch_bounds__(256)
k1(const float* __restrict__ y, const float* __restrict__ Wv) {
    __shared__ float ys_s[32];
    const int bid  = blockIdx.x;
    const int t    = threadIdx.x;
    const int warp = t >> 5;          // 0..7
    const int lane = t & 31;

    // ---- stream: 4 adjacent rows per warp ----
    const int r0 = bid * 32 + warp * 4;
    const float4* p0 = reinterpret_cast<const float4*>(y) + (size_t)r0 * N4;
    const float4* p1 = p0 + N4;
    const float4* p2 = p1 + N4;
    const float4* p3 = p2 + N4;
    const bool tail = (lane < N4 - 32);

    float4 a0 = p0[lane];
    float4 a1 = p1[lane];
    float4 a2 = p2[lane];
    float4 a3 = p3[lane];
    float4 t0 = tail ? p0[lane + 32] : make_float4(0,0,0,0);
    float4 t1 = tail ? p1[lane + 32] : make_float4(0,0,0,0);
    float4 t2 = tail ? p2[lane + 32] : make_float4(0,0,0,0);
    float4 t3 = tail ? p3[lane + 32] : make_float4(0,0,0,0);

    float s0 = a0.x+a0.y+a0.z+a0.w + t0.x+t0.y+t0.z+t0.w;
    float s1 = a1.x+a1.y+a1.z+a1.w + t1.x+t1.y+t1.z+t1.w;
    float s2 = a2.x+a2.y+a2.z+a2.w + t2.x+t2.y+t2.z+t2.w;
    float s3 = a3.x+a3.y+a3.z+a3.w + t3.x+t3.y+t3.z+t3.w;

    #pragma unroll
    for (int o = 16; o; o >>= 1) {
        s0 += __shfl_xor_sync(0xFFFFFFFFu, s0, o);
        s1 += __shfl_xor_sync(0xFFFFFFFFu, s1, o);
        s2 += __shfl_xor_sync(0xFFFFFFFFu, s2, o);
        s3 += __shfl_xor_sync(0xFFFFFFFFu, s3, o);
    }
    if (lane == 0) {
        ys_s[warp * 4 + 0] = s0;
        ys_s[warp * 4 + 1] = s1;
        ys_s[warp * 4 + 2] = s2;
        ys_s[warp * 4 + 3] = s3;
    }
    __syncthreads();

    // ---- partial projection: p[ch] = sum_{j<32} Wv[ch, grp*32+j]*ys_s[j] ----
    // 256 thr = 128 ch x 2 halves; each thread 4 float4 of Wv (64B contiguous).
    {
        const int ch = t >> 1, half = t & 1;
        const int grp = bid & 7;
        const float4* wv4 = reinterpret_cast<const float4*>(Wv)
                          + ch * (Cc / 4) + grp * 8 + half * 4;
        const float* yy = ys_s + half * 16;
        float acc = 0.0f;
        #pragma unroll
        for (int i = 0; i < 4; i++) {
            const float4 w = wv4[i];
            acc += w.x * yy[4*i] + w.y * yy[4*i+1]
                 + w.z * yy[4*i+2] + w.w * yy[4*i+3];
        }
        acc += __shfl_xor_sync(0xFFFFFFFFu, acc, 1);
        if (half == 0) g_tmp_part[bid * CH + ch] = acc;   // coalesced
    }
}

// K2: block bid = (batch b=bid>>3, slice grp=bid&7). ZERO __syncthreads:
// front-batch 8 x LDG.128, then each warp computes the full tmp[128] itself
// (lane holds tmp[4l..4l+3]) and its own 4 zbn values via butterfly dots.
__global__ void __launch_bounds__(256)
k2(const float* __restrict__ x,
   const float* __restrict__ Wz,
   const float* __restrict__ bn_w,
   const float* __restrict__ bn_b,
   const float* __restrict__ bn_m,
   const float* __restrict__ bn_v,
   float* __restrict__ out) {
    const int bid  = blockIdx.x;
    const int t    = threadIdx.x;
    const int warp = t >> 5;
    const int lane = t & 31;

    // ---- 0) front-batched x loads (8 independent LDG.128 per thread) ----
    const int lr = warp * 4;                            // local rows lr..lr+3
    const size_t f4base = ((size_t)bid * 32 + lr) * N4;
    const float4* X = reinterpret_cast<const float4*>(x) + f4base;
    float4*       O = reinterpret_cast<float4*>(out) + f4base;
    const bool tail = (lane < N4 - 32);

    float4 a0 = X[0*N4 + lane];
    float4 a1 = X[1*N4 + lane];
    float4 a2 = X[2*N4 + lane];
    float4 a3 = X[3*N4 + lane];
    float4 t0 = tail ? X[0*N4 + lane + 32] : make_float4(0,0,0,0);
    float4 t1 = tail ? X[1*N4 + lane + 32] : make_float4(0,0,0,0);
    float4 t2 = tail ? X[2*N4 + lane + 32] : make_float4(0,0,0,0);
    float4 t3 = tail ? X[3*N4 + lane + 32] : make_float4(0,0,0,0);

    // ---- 1) warp-local tmp: lane holds tmp[4*lane .. 4*lane+3] ----
    // 8 coalesced LDG.128 (each 512B/warp), fixed-order sum -> deterministic.
    const int b = bid >> 3;
    const float4* P = reinterpret_cast<const float4*>(g_tmp_part)
                    + (size_t)b * 8 * (CH / 4) + lane;
    float4 tp;
    {
        const float4 q0 = P[0 * 32];
        const float4 q1 = P[1 * 32];
        const float4 q2 = P[2 * 32];
        const float4 q3 = P[3 * 32];
        const float4 q4 = P[4 * 32];
        const float4 q5 = P[5 * 32];
        const float4 q6 = P[6 * 32];
        const float4 q7 = P[7 * 32];
        tp.x = ((q0.x + q1.x) + (q2.x + q3.x)) + ((q4.x + q5.x) + (q6.x + q7.x));
        tp.y = ((q0.y + q1.y) + (q2.y + q3.y)) + ((q4.y + q5.y) + (q6.y + q7.y));
        tp.z = ((q0.z + q1.z) + (q2.z + q3.z)) + ((q4.z + q5.z) + (q6.z + q7.z));
        tp.w = ((q0.w + q1.w) + (q2.w + q3.w)) + ((q4.w + q5.w) + (q6.w + q7.w));
    }

    // ---- 2) zbn for this warp's 4 channels: butterfly dots over tmp ----
    const int o0 = (bid & 7) * 32 + lr;
    float acc0, acc1, acc2, acc3;
    {
        const float4* WZ = reinterpret_cast<const float4*>(Wz);
        const float4 w0 = WZ[(o0 + 0) * (CH / 4) + lane];
        const float4 w1 = WZ[(o0 + 1) * (CH / 4) + lane];
        const float4 w2 = WZ[(o0 + 2) * (CH / 4) + lane];
        const float4 w3 = WZ[(o0 + 3) * (CH / 4) + lane];
        acc0 = w0.x*tp.x + w0.y*tp.y + w0.z*tp.z + w0.w*tp.w;
        acc1 = w1.x*tp.x + w1.y*tp.y + w1.z*tp.z + w1.w*tp.w;
        acc2 = w2.x*tp.x + w2.y*tp.y + w2.z*tp.z + w2.w*tp.w;
        acc3 = w3.x*tp.x + w3.y*tp.y + w3.z*tp.z + w3.w*tp.w;
        #pragma unroll
        for (int o = 16; o; o >>= 1) {
            acc0 += __shfl_xor_sync(0xFFFFFFFFu, acc0, o);
            acc1 += __shfl_xor_sync(0xFFFFFFFFu, acc1, o);
            acc2 += __shfl_xor_sync(0xFFFFFFFFu, acc2, o);
            acc3 += __shfl_xor_sync(0xFFFFFFFFu, acc3, o);
        }
    }
    // BN fold (uniform loads within warp: one line each, L1/L2-hot)
    const float s0f = rsqrtf(bn_v[o0 + 0] + EPS) * bn_w[o0 + 0];
    const float s1f = rsqrtf(bn_v[o0 + 1] + EPS) * bn_w[o0 + 1];
    const float s2f = rsqrtf(bn_v[o0 + 2] + EPS) * bn_w[o0 + 2];
    const float s3f = rsqrtf(bn_v[o0 + 3] + EPS) * bn_w[o0 + 3];
    const float z0 = acc0 * s0f + bn_b[o0 + 0] - bn_m[o0 + 0] * s0f;
    const float z1 = acc1 * s1f + bn_b[o0 + 1] - bn_m[o0 + 1] * s1f;
    const float z2 = acc2 * s2f + bn_b[o0 + 2] - bn_m[o0 + 2] * s2f;
    const float z3 = acc3 * s3f + bn_b[o0 + 3] - bn_m[o0 + 3] * s3f;

    // ---- 3) add + store (x values arrived during the preamble) ----
    a0.x += z0; a0.y += z0; a0.z += z0; a0.w += z0;
    a1.x += z1; a1.y += z1; a1.z += z1; a1.w += z1;
    a2.x += z2; a2.y += z2; a2.z += z2; a2.w += z2;
    a3.x += z3; a3.y += z3; a3.z += z3; a3.w += z3;
    O[0*N4 + lane] = a0;
    O[1*N4 + lane] = a1;
    O[2*N4 + lane] = a2;
    O[3*N4 + lane] = a3;

    if (tail) {
        t0.x += z0; t0.y += z0; t0.z += z0; t0.w += z0;
        t1.x += z1; t1.y += z1; t1.z += z1; t1.w += z1;
        t2.x += z2; t2.y += z2; t2.z += z2; t2.w += z2;
        t3.x += z3; t3.y += z3; t3.z += z3; t3.w += z3;
        O[0*N4 + lane + 32] = t0;
        O[1*N4 + lane + 32] = t1;
        O[2*N4 + lane + 32] = t2;
        O[3*N4 + lane + 32] = t3;
    }
}

// ---------------------------------------------------------------------------
// Inputs (metadata order):
//  0:x 1:y 2:Wq 3:Wk 4:Wv 5:Wz 6:bn_weight 7:bn_bias 8:bn_mean 9:bn_var
// ---------------------------------------------------------------------------
extern "C" void kernel_launch(void* const* d_in, const int* in_sizes, int n_in,
                              void* d_out, int out_size) {
    const float* x    = (const float*)d_in[0];
    const float* y    = (const float*)d_in[1];
    const float* Wv   = (const float*)d_in[4];
    const float* Wz   = (const float*)d_in[5];
    const float* bn_w = (const float*)d_in[6];
    const float* bn_b = (const float*)d_in[7];
    const float* bn_m = (const float*)d_in[8];
    const float* bn_v = (const float*)d_in[9];
    float* out = (float*)d_out;

    k1<<<K1_GRID, 256>>>(y, Wv);
    k2<<<K2_GRID, 256>>>(x, Wz, bn_w, bn_b, bn_m, bn_v, out);
}

// round 13
// speedup vs baseline: 1.1460x; 1.1460x over previous
#include <cuda_runtime.h>

// Shapes (fixed by the problem)
#define Bb 256
#define Cc 256
#define CH 128
#define NN 196               // H*W = 14*14
#define N4 49                // float4s per channel row
#define EPS 1e-5f

#define K1_GRID 2048         // block = (batch, 32-channel slice)
#define K2_GRID 2048         // block = (batch, 32-channel slice)

// Scratch (__device__ globals; fully overwritten per launch -> replay-safe)
// g_tmp_part[bid][ch]: partial of tmp[b,ch] = (Wv @ ysum[b])[ch] from slice grp.
__device__ float g_tmp_part[K1_GRID * CH];   // 1 MB

// ---------------------------------------------------------------------------
// Math: softmax over a singleton axis == 1 -> attention collapses to the
// spatial sum (Wq, Wk dead):
//   tmp[b]   = Wv @ (sum_n y[b,:,n])
//   zbn[b,o] = BN( Wz[o,:] . tmp[b] );   out = x + bcast(zbn)
// tmp distributes over 32-channel slices -> no cross-block dependency in K1.
// ---------------------------------------------------------------------------

// K1 (proven 512-thr shape): block bid covers rows [bid*32, bid*32+32).
// 16 warps x 2 rows, 4 front-batched LDG.128, then the Wv-slice partial.
__global__ void __launch_bounds__(512)
k1(const float* __restrict__ y, const float* __restrict__ Wv) {
    __shared__ float ys_s[32];
    const int bid  = blockIdx.x;
    const int t    = threadIdx.x;
    const int warp = t >> 5;
    const int lane = t & 31;

    // ---- stream: 2 adjacent rows per warp, 4 front-batched LDG.128 ----
    const int r0 = bid * 32 + warp * 2;
    const float4* p0 = reinterpret_cast<const float4*>(y) + (size_t)r0 * N4;
    const float4* p1 = p0 + N4;

    float4 a0 = p0[lane];
    float4 a1 = (lane < N4 - 32) ? p0[lane + 32] : make_float4(0,0,0,0);
    float4 b0 = p1[lane];
    float4 b1 = (lane < N4 - 32) ? p1[lane + 32] : make_float4(0,0,0,0);

    float s0 = a0.x + a0.y + a0.z + a0.w + a1.x + a1.y + a1.z + a1.w;
    float s1 = b0.x + b0.y + b0.z + b0.w + b1.x + b1.y + b1.z + b1.w;
    #pragma unroll
    for (int o = 16; o; o >>= 1) {
        s0 += __shfl_xor_sync(0xFFFFFFFFu, s0, o);
        s1 += __shfl_xor_sync(0xFFFFFFFFu, s1, o);
    }
    if (lane == 0) { ys_s[warp * 2] = s0; ys_s[warp * 2 + 1] = s1; }
    __syncthreads();

    // ---- partial projection: p[ch] = sum_{j<32} Wv[ch, grp*32+j]*ys_s[j] ----
    {
        const int ch = t >> 2, part = t & 3;
        const int grp = bid & 7;
        const float4* wv4 = reinterpret_cast<const float4*>(Wv)
                          + ch * (Cc / 4) + grp * 8 + part * 2;
        float acc = 0.0f;
        #pragma unroll
        for (int i = 0; i < 2; i++) {
            const float4 w = wv4[i];
            const float* yy = ys_s + (part * 2 + i) * 4;
            acc += w.x * yy[0] + w.y * yy[1] + w.z * yy[2] + w.w * yy[3];
        }
        acc += __shfl_xor_sync(0xFFFFFFFFu, acc, 1);
        acc += __shfl_xor_sync(0xFFFFFFFFu, acc, 2);
        if (part == 0) g_tmp_part[bid * CH + ch] = acc;   // coalesced
    }
}

// K2: block bid = (batch b=bid>>3, slice grp=bid&7).
// LOAD ORDER = CONSUMPTION ORDER (L1tex completes loads in issue order):
//   1) preamble loads (tmp partials + Wz rows)  -- consumed first
//   2) 8 front-batched x LDG.128                 -- consumed last
// Preamble computes while x is in flight; zero wasted queue wait.
__global__ void __launch_bounds__(256)
k2(const float* __restrict__ x,
   const float* __restrict__ Wz,
   const float* __restrict__ bn_w,
   const float* __restrict__ bn_b,
   const float* __restrict__ bn_m,
   const float* __restrict__ bn_v,
   float* __restrict__ out) {
    __shared__ __align__(16) float tmp_s[CH];
    __shared__ float zloc[32];
    const int bid  = blockIdx.x;
    const int t    = threadIdx.x;
    const int warp = t >> 5;
    const int lane = t & 31;

    // ---- 1a) issue preamble loads FIRST ----
    // tmp partials: 128 ch x 2 halves (4 partials each)
    const int chA = t >> 1, half = t & 1;
    const int b   = bid >> 3;
    const float* pp = g_tmp_part + (b * 8 + half * 4) * CH + chA;
    const float q0 = __ldg(pp);
    const float q1 = __ldg(pp + CH);
    const float q2 = __ldg(pp + 2 * CH);
    const float q3 = __ldg(pp + 3 * CH);

    // Wz rows for phase B: 32 ch x 8 parts, 64B/thread contiguous
    const int och = t >> 3, part8 = t & 7;
    const int o   = (bid & 7) * 32 + och;
    const float4* wz4 = reinterpret_cast<const float4*>(Wz)
                      + o * (CH / 4) + part8 * 4;
    const float4 w0 = __ldg(wz4 + 0);
    const float4 w1 = __ldg(wz4 + 1);
    const float4 w2 = __ldg(wz4 + 2);
    const float4 w3 = __ldg(wz4 + 3);

    // ---- 1b) then the 8 x loads (consumed last, land behind preamble) ----
    const int lr = warp * 4;                            // local rows lr..lr+3
    const size_t f4base = ((size_t)bid * 32 + lr) * N4;
    const float4* X = reinterpret_cast<const float4*>(x) + f4base;
    float4*       O = reinterpret_cast<float4*>(out) + f4base;
    const bool tail = (lane < N4 - 32);

    float4 a0 = X[0*N4 + lane];
    float4 a1 = X[1*N4 + lane];
    float4 a2 = X[2*N4 + lane];
    float4 a3 = X[3*N4 + lane];
    float4 t0 = tail ? X[0*N4 + lane + 32] : make_float4(0,0,0,0);
    float4 t1 = tail ? X[1*N4 + lane + 32] : make_float4(0,0,0,0);
    float4 t2 = tail ? X[2*N4 + lane + 32] : make_float4(0,0,0,0);
    float4 t3 = tail ? X[3*N4 + lane + 32] : make_float4(0,0,0,0);

    // ---- 2) tmp[b] (fixed-order sum -> deterministic) ----
    {
        float a = (q0 + q1) + (q2 + q3);
        a += __shfl_xor_sync(0xFFFFFFFFu, a, 1);        // combine halves
        if (half == 0) tmp_s[chA] = a;
    }
    __syncthreads();

    // ---- 3) zbn for this block's 32 channels ----
    {
        const float4* tp4 = reinterpret_cast<const float4*>(tmp_s) + part8 * 4;
        const float4 v0 = tp4[0];
        const float4 v1 = tp4[1];
        const float4 v2 = tp4[2];
        const float4 v3 = tp4[3];
        float acc = (w0.x*v0.x + w0.y*v0.y + w0.z*v0.z + w0.w*v0.w)
                  + (w1.x*v1.x + w1.y*v1.y + w1.z*v1.z + w1.w*v1.w)
                  + (w2.x*v2.x + w2.y*v2.y + w2.z*v2.z + w2.w*v2.w)
                  + (w3.x*v3.x + w3.y*v3.y + w3.z*v3.z + w3.w*v3.w);
        acc += __shfl_xor_sync(0xFFFFFFFFu, acc, 1);
        acc += __shfl_xor_sync(0xFFFFFFFFu, acc, 2);
        acc += __shfl_xor_sync(0xFFFFFFFFu, acc, 4);
        if (part8 == 0) {
            const float s = rsqrtf(bn_v[o] + EPS) * bn_w[o];
            zloc[och] = acc * s + bn_b[o] - bn_m[o] * s;
        }
    }
    __syncthreads();

    // ---- 4) add + store (x landed during the preamble compute) ----
    const float z0 = zloc[lr + 0];
    const float z1 = zloc[lr + 1];
    const float z2 = zloc[lr + 2];
    const float z3 = zloc[lr + 3];

    a0.x += z0; a0.y += z0; a0.z += z0; a0.w += z0;
    a1.x += z1; a1.y += z1; a1.z += z1; a1.w += z1;
    a2.x += z2; a2.y += z2; a2.z += z2; a2.w += z2;
    a3.x += z3; a3.y += z3; a3.z += z3; a3.w += z3;
    O[0*N4 + lane] = a0;
    O[1*N4 + lane] = a1;
    O[2*N4 + lane] = a2;
    O[3*N4 + lane] = a3;

    if (tail) {
        t0.x += z0; t0.y += z0; t0.z += z0; t0.w += z0;
        t1.x += z1; t1.y += z1; t1.z += z1; t1.w += z1;
        t2.x += z2; t2.y += z2; t2.z += z2; t2.w += z2;
        t3.x += z3; t3.y += z3; t3.z += z3; t3.w += z3;
        O[0*N4 + lane + 32] = t0;
        O[1*N4 + lane + 32] = t1;
        O[2*N4 + lane + 32] = t2;
        O[3*N4 + lane + 32] = t3;
    }
}

// ---------------------------------------------------------------------------
// Inputs (metadata order):
//  0:x 1:y 2:Wq 3:Wk 4:Wv 5:Wz 6:bn_weight 7:bn_bias 8:bn_mean 9:bn_var
// ---------------------------------------------------------------------------
extern "C" void kernel_launch(void* const* d_in, const int* in_sizes, int n_in,
                              void* d_out, int out_size) {
    const float* x    = (const float*)d_in[0];
    const float* y    = (const float*)d_in[1];
    const float* Wv   = (const float*)d_in[4];
    const float* Wz   = (const float*)d_in[5];
    const float* bn_w = (const float*)d_in[6];
    const float* bn_b = (const float*)d_in[7];
    const float* bn_m = (const float*)d_in[8];
    const float* bn_v = (const float*)d_in[9];
    float* out = (float*)d_out;

    k1<<<K1_GRID, 512>>>(y, Wv);
    k2<<<K2_GRID, 256>>>(x, Wz, bn_w, bn_b, bn_m, bn_v, out);
}